// round 5
// baseline (speedup 1.0000x reference)
#include <cuda_runtime.h>
#include <cuda_bf16.h>
#include <cstdint>

#define MROWS   131072
#define NDIM    16
#define NBINS   8
#define NELEM   (MROWS * NDIM)          // 2,097,152
#define MIN_BW  0.001f
#define MIN_KS  0.001f

#define TILE    256
#define NTILES  (NELEM / TILE)          // 8192
#define GRIDSZ  592                     // ~4 persistent blocks per SM (148 SMs)
#define W_TILE_BYTES  (TILE * 8 * 4)    // 8192
#define S_TILE_BYTES  (TILE * 7 * 4)    // 7168
#define TX_BYTES      (2 * (W_TILE_BYTES + W_TILE_BYTES + S_TILE_BYTES))  // 47104

__device__ __forceinline__ uint32_t smem_u32(const void* p) {
    uint32_t a;
    asm("{ .reg .u64 t; cvta.to.shared.u64 t, %1; cvt.u32.u64 %0, t; }"
        : "=r"(a) : "l"(p));
    return a;
}

__device__ __forceinline__ void bulk_g2s(uint32_t dst, const float* src,
                                         uint32_t bytes, uint32_t mbar) {
    asm volatile(
        "cp.async.bulk.shared::cta.global.mbarrier::complete_tx::bytes "
        "[%0], [%1], %2, [%3];"
        :: "r"(dst), "l"(src), "r"(bytes), "r"(mbar) : "memory");
}

__device__ __forceinline__ void mbar_wait(uint32_t mb, uint32_t parity) {
    uint32_t done;
    asm volatile(
        "{\n\t.reg .pred p;\n\t"
        "mbarrier.try_wait.parity.acquire.cta.shared::cta.b64 p, [%1], %2;\n\t"
        "selp.b32 %0, 1, 0, p;\n\t}"
        : "=r"(done) : "r"(mb), "r"(parity) : "memory");
    if (!done) {
        asm volatile(
            "{\n\t.reg .pred P1;\n\t"
            "W0_%=:\n\t"
            "mbarrier.try_wait.parity.acquire.cta.shared::cta.b64 P1, [%0], %1, 0x989680;\n\t"
            "@P1 bra.uni W1_%=;\n\t"
            "bra.uni W0_%=;\n\t"
            "W1_%=:\n\t}"
            :: "r"(mb), "r"(parity) : "memory");
    }
}

__device__ __forceinline__ float softplus_f(float v) {
    return (v > 15.0f) ? v : __logf(1.0f + __expf(v));
}

// One RQS transform: shift -> spline -> unshift. Operand rows live in smem.
__device__ __forceinline__ float rqs_step(float x, float shift,
                                          const float* wrow,
                                          const float* hrow,
                                          const float* srow,
                                          float& ladsum)
{
    const float cdom = 2.0f - (float)NBINS * MIN_BW;   // 1.992

    float arg = x + shift + 1.0f;
    if (arg >= 2.0f) arg -= 2.0f;
    float xs = arg - 1.0f;

    float4 wa = *reinterpret_cast<const float4*>(wrow);
    float4 wb = *reinterpret_cast<const float4*>(wrow + 4);
    float4 ha = *reinterpret_cast<const float4*>(hrow);
    float4 hb = *reinterpret_cast<const float4*>(hrow + 4);

    float ew[8], eh[8];
    ew[0] = __expf(wa.x); ew[1] = __expf(wa.y); ew[2] = __expf(wa.z); ew[3] = __expf(wa.w);
    ew[4] = __expf(wb.x); ew[5] = __expf(wb.y); ew[6] = __expf(wb.z); ew[7] = __expf(wb.w);
    eh[0] = __expf(ha.x); eh[1] = __expf(ha.y); eh[2] = __expf(ha.z); eh[3] = __expf(ha.w);
    eh[4] = __expf(hb.x); eh[5] = __expf(hb.y); eh[6] = __expf(hb.z); eh[7] = __expf(hb.w);

    float sw = ((ew[0] + ew[1]) + (ew[2] + ew[3])) + ((ew[4] + ew[5]) + (ew[6] + ew[7]));
    float sh = ((eh[0] + eh[1]) + (eh[2] + eh[3])) + ((eh[4] + eh[5]) + (eh[6] + eh[7]));

    float cw = __fdividef(cdom, sw);
    float ch = __fdividef(cdom, sh);

    float bw[8], bh[8];
    #pragma unroll
    for (int j = 0; j < 8; ++j) {
        bw[j] = ew[j] * cw + MIN_BW;
        bh[j] = eh[j] * ch + MIN_BW;
    }

    float cum = -1.0f + bw[0];
    float x0  = -1.0f;
    float y0  = -1.0f;
    float wk  = bw[0], hk = bh[0];
    int   idx = 0;
    #pragma unroll
    for (int j = 0; j < 7; ++j) {
        if (xs >= cum) {
            idx = j + 1;
            x0  = cum;
            y0 += bh[j];
            wk  = bw[j + 1];
            hk  = bh[j + 1];
        }
        if (j < 6) cum += bw[j + 1];
    }

    int a0 = (idx > 0) ? idx - 1 : 0;
    int a1 = (idx < 7) ? idx : 6;
    float v0 = srow[a0];
    float v1 = srow[a1];
    float d0 = (idx > 0) ? softplus_f(v0) + MIN_KS : 1.0f;
    float d1 = (idx < 7) ? softplus_f(v1) + MIN_KS : 1.0f;

    float rwk  = __fdividef(1.0f, wk);
    float sk   = hk * rwk;
    float t    = (xs - x0) * rwk;
    float omt  = 1.0f - t;
    float tomt = t * omt;
    float denom = sk + (d1 + d0 - 2.0f * sk) * tomt;
    float rden  = __fdividef(1.0f, denom);
    float y = y0 + hk * (sk * t * t + d0 * tomt) * rden;

    float numer = d1 * t * t + 2.0f * sk * tomt + d0 * omt * omt;
    ladsum += __logf(sk * sk * numer * rden * rden);

    float arg2 = y - shift + 3.0f;
    if (arg2 >= 2.0f) arg2 -= 2.0f;
    if (arg2 >= 2.0f) arg2 -= 2.0f;
    return arg2 - 1.0f;
}

struct Tails { const float *w, *h, *s; };

__device__ __forceinline__ void issue_tile(int tile, int stage, uint32_t mb,
                                           float w_s[2][TILE * 8],
                                           float h_s[2][TILE * 8],
                                           float s_s[2][TILE * 7],
                                           const float* w, const float* h,
                                           const float* s)
{
    asm volatile("mbarrier.arrive.expect_tx.shared.b64 _, [%0], %1;"
                 :: "r"(mb), "r"((uint32_t)TX_BYTES) : "memory");
    size_t o8 = (size_t)tile * (TILE * 8);
    size_t o7 = (size_t)tile * (TILE * 7);
    bulk_g2s(smem_u32(&w_s[stage][0]),            w + o8,                      W_TILE_BYTES, mb);
    bulk_g2s(smem_u32(&w_s[stage][TILE * 4]),     w + (size_t)NELEM * 8 + o8,  W_TILE_BYTES, mb);
    bulk_g2s(smem_u32(&h_s[stage][0]),            h + o8,                      W_TILE_BYTES, mb);
    bulk_g2s(smem_u32(&h_s[stage][TILE * 4]),     h + (size_t)NELEM * 8 + o8,  W_TILE_BYTES, mb);
    bulk_g2s(smem_u32(&s_s[stage][0]),            s + o7,                      S_TILE_BYTES / 2, mb);
    bulk_g2s(smem_u32(&s_s[stage][0]) + S_TILE_BYTES / 2,
             s + o7 + TILE * 7 / 2,                                            S_TILE_BYTES / 2, mb);
    // NOTE: second s half above is transform-0 tail + we still need transform-1 s.
}

__global__ __launch_bounds__(256)
void rqs_coupling_kernel(const float* __restrict__ x_in,
                         const float* __restrict__ w,
                         const float* __restrict__ h,
                         const float* __restrict__ s,
                         const float* __restrict__ shifts,
                         float* __restrict__ out)
{
    // Stage layout: per stage, w_s holds [tr0: TILE*8 | tr1: TILE*8] etc.
    __shared__ __align__(16) float w_s[2][2 * TILE * 8];   // 32 KB
    __shared__ __align__(16) float h_s[2][2 * TILE * 8];   // 32 KB
    __shared__ __align__(16) float s_s[2][2 * TILE * 7];   // 28 KB
    __shared__ __align__(8)  unsigned long long mbar[2];

    int tid = threadIdx.x;
    uint32_t mb0 = smem_u32(&mbar[0]);
    uint32_t mb1 = smem_u32(&mbar[1]);

    if (tid == 0) {
        asm volatile("mbarrier.init.shared.b64 [%0], %1;" :: "r"(mb0), "r"(1) : "memory");
        asm volatile("mbarrier.init.shared.b64 [%0], %1;" :: "r"(mb1), "r"(1) : "memory");
        asm volatile("fence.proxy.async.shared::cta;" ::: "memory");
    }
    __syncthreads();

    // local TMA issue helper (full tile: both transforms)
    auto post = [&](int tile, int stage) {
        uint32_t mb = stage ? mb1 : mb0;
        asm volatile("mbarrier.arrive.expect_tx.shared.b64 _, [%0], %1;"
                     :: "r"(mb), "r"((uint32_t)TX_BYTES) : "memory");
        size_t o8 = (size_t)tile * (TILE * 8);
        size_t o7 = (size_t)tile * (TILE * 7);
        bulk_g2s(smem_u32(&w_s[stage][0]),        w + o8,                     W_TILE_BYTES, mb);
        bulk_g2s(smem_u32(&w_s[stage][TILE * 8]), w + (size_t)NELEM * 8 + o8, W_TILE_BYTES, mb);
        bulk_g2s(smem_u32(&h_s[stage][0]),        h + o8,                     W_TILE_BYTES, mb);
        bulk_g2s(smem_u32(&h_s[stage][TILE * 8]), h + (size_t)NELEM * 8 + o8, W_TILE_BYTES, mb);
        bulk_g2s(smem_u32(&s_s[stage][0]),        s + o7,                     S_TILE_BYTES, mb);
        bulk_g2s(smem_u32(&s_s[stage][TILE * 7]), s + (size_t)NELEM * 7 + o7, S_TILE_BYTES, mb);
    };

    int t0 = blockIdx.x;                 // first tile for this block
    if (tid == 0) {
        post(t0, 0);
        if (t0 + GRIDSZ < NTILES) post(t0 + GRIDSZ, 1);
    }

    uint32_t parity[2] = {0u, 0u};
    int stage = 0;

    for (int tile = t0; tile < NTILES; tile += GRIDSZ) {
        int e = tile * TILE + tid;

        // independent scalar loads overlap the wait
        float x   = __ldcs(x_in + e);
        float sh0 = __ldcs(shifts + e);
        float sh1 = __ldcs(shifts + NELEM + e);

        uint32_t mb = stage ? mb1 : mb0;
        mbar_wait(mb, parity[stage]);
        parity[stage] ^= 1u;

        float ladsum = 0.0f;
        x = rqs_step(x, sh0, &w_s[stage][8 * tid],
                             &h_s[stage][8 * tid],
                             &s_s[stage][7 * tid], ladsum);
        x = rqs_step(x, sh1, &w_s[stage][TILE * 8 + 8 * tid],
                             &h_s[stage][TILE * 8 + 8 * tid],
                             &s_s[stage][TILE * 7 + 7 * tid], ladsum);

        __stcs(out + e, x);
        __stcs(out + NELEM + e, ladsum);

        __syncthreads();                 // everyone done reading this stage
        int next = tile + 2 * GRIDSZ;
        if (tid == 0 && next < NTILES) {
            asm volatile("fence.proxy.async.shared::cta;" ::: "memory");
            post(next, stage);
        }
        stage ^= 1;
    }
}

extern "C" void kernel_launch(void* const* d_in, const int* in_sizes, int n_in,
                              void* d_out, int out_size) {
    const float* x      = (const float*)d_in[0];
    const float* w      = (const float*)d_in[1];
    const float* h      = (const float*)d_in[2];
    const float* s      = (const float*)d_in[3];
    const float* shifts = (const float*)d_in[4];
    float* out = (float*)d_out;

    rqs_coupling_kernel<<<GRIDSZ, TILE>>>(x, w, h, s, shifts, out);
}

// round 6
// speedup vs baseline: 1.1171x; 1.1171x over previous
#include <cuda_runtime.h>
#include <cuda_bf16.h>

#define MROWS   131072
#define NDIM    16
#define NBINS   8
#define NELEM   (MROWS * NDIM)          // 2,097,152
#define MIN_BW  0.001f
#define MIN_KS  0.001f

__device__ __forceinline__ float softplus_f(float v) {
    return (v > 15.0f) ? v : __logf(1.0f + __expf(v));
}

__device__ __forceinline__ float4 ldcs4(const float* p) {
    return __ldcs(reinterpret_cast<const float4*>(p));
}

// Search + spline for one transform, bins (bw/bh) already normalized.
__device__ __forceinline__ float spline_eval(float x, float shift,
                                             const float* bw, const float* bh,
                                             const float* srow,
                                             float& ladsum)
{
    // forward periodic shift: arg = x + shift + 1 in [0,3); mod 2, -1
    float arg = x + shift + 1.0f;
    if (arg >= 2.0f) arg -= 2.0f;
    float xs = arg - 1.0f;

    // fused bin search + gather (predicated register selects)
    float cum = -1.0f + bw[0];
    float x0  = -1.0f;
    float y0  = -1.0f;
    float wk  = bw[0], hk = bh[0];
    int   idx = 0;
    #pragma unroll
    for (int j = 0; j < 7; ++j) {
        if (xs >= cum) {
            idx = j + 1;
            x0  = cum;
            y0 += bh[j];
            wk  = bw[j + 1];
            hk  = bh[j + 1];
        }
        if (j < 6) cum += bw[j + 1];
    }

    // flanking knot slopes from smem (clamped address, predicated value)
    int a0 = (idx > 0) ? idx - 1 : 0;
    int a1 = (idx < 7) ? idx : 6;
    float v0 = srow[a0];
    float v1 = srow[a1];
    float d0 = (idx > 0) ? softplus_f(v0) + MIN_KS : 1.0f;
    float d1 = (idx < 7) ? softplus_f(v1) + MIN_KS : 1.0f;

    float rwk  = __fdividef(1.0f, wk);
    float sk   = hk * rwk;
    float t    = (xs - x0) * rwk;
    float omt  = 1.0f - t;
    float tomt = t * omt;
    float denom = sk + (d1 + d0 - 2.0f * sk) * tomt;
    float rden  = __fdividef(1.0f, denom);
    float y = y0 + hk * (sk * t * t + d0 * tomt) * rden;

    float numer = d1 * t * t + 2.0f * sk * tomt + d0 * omt * omt;
    ladsum += __logf(sk * sk * numer * rden * rden);

    // inverse periodic shift: arg2 = y - shift + 3 in [1, 4]
    float arg2 = y - shift + 3.0f;
    if (arg2 >= 2.0f) arg2 -= 2.0f;
    if (arg2 >= 2.0f) arg2 -= 2.0f;
    return arg2 - 1.0f;
}

__device__ __forceinline__ void exp8(const float4& a, const float4& b, float* e) {
    e[0] = __expf(a.x); e[1] = __expf(a.y); e[2] = __expf(a.z); e[3] = __expf(a.w);
    e[4] = __expf(b.x); e[5] = __expf(b.y); e[6] = __expf(b.z); e[7] = __expf(b.w);
}

__device__ __forceinline__ float sum8(const float* e) {
    return ((e[0] + e[1]) + (e[2] + e[3])) + ((e[4] + e[5]) + (e[6] + e[7]));
}

__global__ __launch_bounds__(256)
void rqs_coupling_kernel(const float* __restrict__ x_in,
                         const float* __restrict__ w,
                         const float* __restrict__ h,
                         const float* __restrict__ s,
                         const float* __restrict__ shifts,
                         float* __restrict__ out)
{
    // s slope staging: [transform][warp][224 floats] — warp-private regions
    __shared__ __align__(16) float s_stage[2][8][224];

    const float cdom = 2.0f - (float)NBINS * MIN_BW;   // 1.992

    int e    = blockIdx.x * 256 + threadIdx.x;
    int lane = threadIdx.x & 31;
    int warp = threadIdx.x >> 5;

    size_t b0_128 = (size_t)e * 8u;
    size_t b1_128 = ((size_t)NELEM + (size_t)e) * 8u;

    size_t sbase0 = (size_t)(blockIdx.x * 256 + warp * 32) * 7u;
    size_t sbase1 = sbase0 + (size_t)NELEM * 7u;

    // ---- front-batched, fully independent, fully coalesced loads ----
    float  x   = __ldcs(x_in + e);
    float  sh0 = __ldcs(shifts + e);
    float  sh1 = __ldcs(shifts + NELEM + e);
    float4 w0a = ldcs4(w + b0_128);     float4 w0b = ldcs4(w + b0_128 + 4);
    float4 h0a = ldcs4(h + b0_128);     float4 h0b = ldcs4(h + b0_128 + 4);
    float4 w1a = ldcs4(w + b1_128);     float4 w1b = ldcs4(w + b1_128 + 4);
    float4 h1a = ldcs4(h + b1_128);     float4 h1b = ldcs4(h + b1_128 + 4);

    // cooperative s loads: 224 floats per warp per transform
    float4 sv00 = ldcs4(s + sbase0 + 4 * lane);
    float4 sv10 = ldcs4(s + sbase1 + 4 * lane);
    float4 sv01 = make_float4(0.f, 0.f, 0.f, 0.f);
    float4 sv11 = make_float4(0.f, 0.f, 0.f, 0.f);
    if (lane < 24) {
        sv01 = ldcs4(s + sbase0 + 128 + 4 * lane);
        sv11 = ldcs4(s + sbase1 + 128 + 4 * lane);
    }

    *reinterpret_cast<float4*>(&s_stage[0][warp][4 * lane]) = sv00;
    *reinterpret_cast<float4*>(&s_stage[1][warp][4 * lane]) = sv10;
    if (lane < 24) {
        *reinterpret_cast<float4*>(&s_stage[0][warp][128 + 4 * lane]) = sv01;
        *reinterpret_cast<float4*>(&s_stage[1][warp][128 + 4 * lane]) = sv11;
    }
    __syncwarp();

    const float* srow0 = &s_stage[0][warp][7 * lane];
    const float* srow1 = &s_stage[1][warp][7 * lane];

    // ---- interleaved softmax prep for BOTH transforms (ILP-2) ----
    float ew0[8], eh0[8], ew1[8], eh1[8];
    exp8(w0a, w0b, ew0);
    exp8(w1a, w1b, ew1);            // independent chain overlaps tr0's
    exp8(h0a, h0b, eh0);
    exp8(h1a, h1b, eh1);

    float cw0 = __fdividef(cdom, sum8(ew0));
    float cw1 = __fdividef(cdom, sum8(ew1));
    float ch0 = __fdividef(cdom, sum8(eh0));
    float ch1 = __fdividef(cdom, sum8(eh1));

    float bw0[8], bh0[8];
    #pragma unroll
    for (int j = 0; j < 8; ++j) {
        bw0[j] = ew0[j] * cw0 + MIN_BW;
        bh0[j] = eh0[j] * ch0 + MIN_BW;
    }

    float ladsum = 0.0f;
    x = spline_eval(x, sh0, bw0, bh0, srow0, ladsum);

    float bw1[8], bh1[8];
    #pragma unroll
    for (int j = 0; j < 8; ++j) {
        bw1[j] = ew1[j] * cw1 + MIN_BW;
        bh1[j] = eh1[j] * ch1 + MIN_BW;
    }

    x = spline_eval(x, sh1, bw1, bh1, srow1, ladsum);

    __stcs(out + e, x);
    __stcs(out + NELEM + e, ladsum);
}

extern "C" void kernel_launch(void* const* d_in, const int* in_sizes, int n_in,
                              void* d_out, int out_size) {
    const float* x      = (const float*)d_in[0];
    const float* w      = (const float*)d_in[1];
    const float* h      = (const float*)d_in[2];
    const float* s      = (const float*)d_in[3];
    const float* shifts = (const float*)d_in[4];
    float* out = (float*)d_out;

    rqs_coupling_kernel<<<NELEM / 256, 256>>>(x, w, h, s, shifts, out);
}